// round 4
// baseline (speedup 1.0000x reference)
#include <cuda_runtime.h>
#include <cuda_bf16.h>
#include <math.h>

// ---------------------------------------------------------------------------
// CSBrainLLMVQ. fp32 throughout; GEMMs use fma.rn.f32x2 with MOV-free inner
// loops: A pre-duplicated in smem (u64), B read as ulonglong2 (packed pairs).
// Numerics: bit-identical to R3 (same lane pairing, same k-order, same GN expr).
// ---------------------------------------------------------------------------

#define BB   32
#define CHN  19
#define NPP  30
#define PSZ  200
#define RR   570
#define TT   18240
#define DMD  200
#define LLM  4096
#define KCB  4096
#define C25  25
#define W8   8
#define HTOT (BB*C25*RR*W8)
#define PETOT (TT*DMD)
#define NFREQ 101

__device__ float g_bufA[HTOT];
__device__ float g_bufB[HTOT];
__device__ float g_pe[PETOT];
__device__ float g_spec[TT*NFREQ];
__device__ float g_G[KCB*DMD];
__device__ float g_c0[KCB];
__device__ float g_cout[KCB*DMD];
__device__ int   g_idx[TT];
__device__ float g_mean[BB*5];
__device__ float g_rstd[BB*5];

__device__ __forceinline__ float gelu_exact(float v) {
    return 0.5f * v * (1.0f + erff(v * 0.70710678118654752f));
}

#define PACKDUP(dst, a) \
    asm("mov.b64 %0, {%1, %1};" : "=l"(dst) : "r"(__float_as_uint(a)))
#define FMA2(acc, a, b) \
    asm("fma.rn.f32x2 %0, %1, %2, %0;" : "+l"(acc) : "l"(a), "l"(b))
#define UNPK2(lo, hi, v) \
    asm("mov.b64 {%0, %1}, %2;" : "=r"(lo), "=r"(hi) : "l"(v))

// ---------------------------------------------------------------------------
__global__ __launch_bounds__(256) void k_conv1(const float* __restrict__ x,
                                               const float* __restrict__ w,
                                               const float* __restrict__ bias) {
    int br = blockIdx.x;
    int b = br / RR, r = br % RR;
    __shared__ float xs[PSZ];
    __shared__ float ws[C25 * 49];
    __shared__ float bs[C25];
    int t = threadIdx.x;
    if (t < PSZ) xs[t] = x[(size_t)br * PSZ + t];
    for (int i = t; i < C25 * 49; i += 256) ws[i] = w[i];
    if (t < C25) bs[t] = bias[t];
    __syncthreads();
    if (t < 200) {
        int oc = t >> 3, ow = t & 7;
        float acc = bs[oc];
        int base = ow * 25 - 24;
        #pragma unroll 7
        for (int k = 0; k < 49; k++) {
            int p = base + k;
            if (p >= 0 && p < PSZ) acc += xs[p] * ws[oc * 49 + k];
        }
        g_bufA[(((size_t)b * C25 + oc) * RR + r) * W8 + ow] = acc;
    }
}

// ---------------------------------------------------------------------------
__global__ __launch_bounds__(256) void k_gnstats(const float* __restrict__ h) {
    int bg = blockIdx.x;
    int b = bg / 5, g = bg % 5;
    float s1 = 0.f, s2 = 0.f;
    const int per = RR * W8;
    for (int i = threadIdx.x; i < 5 * per; i += 256) {
        int oc = g * 5 + i / per;
        int rw = i % per;
        float v = h[(size_t)(b * C25 + oc) * per + rw];
        s1 += v; s2 += v * v;
    }
    __shared__ float r1[256], r2[256];
    int t = threadIdx.x;
    r1[t] = s1; r2[t] = s2;
    __syncthreads();
    for (int s = 128; s > 0; s >>= 1) {
        if (t < s) { r1[t] += r1[t + s]; r2[t] += r2[t + s]; }
        __syncthreads();
    }
    if (t == 0) {
        float m = r1[0] / 22800.f;
        float var = r2[0] / 22800.f - m * m;
        g_mean[bg] = m;
        g_rstd[bg] = rsqrtf(var + 1e-5f);
    }
}

// ---------------------------------------------------------------------------
__global__ __launch_bounds__(256) void k_conv3x(const float* __restrict__ in,
                                                const float* __restrict__ w,
                                                const float* __restrict__ bias,
                                                const float* __restrict__ gns,
                                                const float* __restrict__ gnb,
                                                float* __restrict__ out) {
    int bi = blockIdx.x;
    int b = bi / 72, rt = bi % 72;
    int r0 = rt * 8;
    int nrows = min(8, RR - r0);
    __shared__ float sIn[C25][8][W8];
    __shared__ float sW[C25 * C25 * 3];
    __shared__ float sB[C25];
    __shared__ float sMean[C25], sRstd[C25], sSc[C25], sBi[C25];
    int t = threadIdx.x;
    for (int i = t; i < C25 * C25 * 3; i += 256) sW[i] = w[i];
    if (t < C25) {
        sB[t] = bias[t];
        int bg = b * 5 + t / 5;
        sMean[t] = g_mean[bg];
        sRstd[t] = g_rstd[bg];
        sSc[t]   = gns[t];
        sBi[t]   = gnb[t];
    }
    for (int i = t; i < C25 * nrows * W8; i += 256) {
        int ic = i / (nrows * W8);
        int lr = (i / W8) % nrows;
        int ww = i & 7;
        sIn[ic][lr][ww] = in[(((size_t)b * C25 + ic) * RR + r0 + lr) * W8 + ww];
    }
    __syncthreads();
    for (int i = t; i < C25 * nrows * W8; i += 256) {
        int ic = i / (nrows * W8);
        int lr = (i / W8) % nrows;
        int ww = i & 7;
        float v = (sIn[ic][lr][ww] - sMean[ic]) * sRstd[ic] * sSc[ic] + sBi[ic];
        sIn[ic][lr][ww] = gelu_exact(v);
    }
    __syncthreads();
    if (t < 200) {
        int oc = t >> 3, ww = t & 7;
        for (int lr = 0; lr < nrows; lr++) {
            float acc = sB[oc];
            #pragma unroll
            for (int ic = 0; ic < C25; ic++) {
                const float* wp = &sW[(oc * C25 + ic) * 3];
                if (ww > 0) acc += sIn[ic][lr][ww - 1] * wp[0];
                acc += sIn[ic][lr][ww] * wp[1];
                if (ww < 7) acc += sIn[ic][lr][ww + 1] * wp[2];
            }
            out[(((size_t)b * C25 + oc) * RR + r0 + lr) * W8 + ww] = acc;
        }
    }
}

// ---------------------------------------------------------------------------
__global__ __launch_bounds__(256) void k_dft(const float* __restrict__ x) {
    __shared__ float xs[2][PSZ], twc[PSZ], tws[PSZ];
    int t = threadIdx.x;
    const float* xp = x + (size_t)blockIdx.x * (2 * PSZ);
    for (int i = t; i < 2 * PSZ; i += 256) ((float*)xs)[i] = xp[i];
    if (t < PSZ) {
        float ang = 6.283185307179586f * (float)t / 200.f;
        twc[t] = cosf(ang);
        tws[t] = sinf(ang);
    }
    __syncthreads();
    if (t < 2 * NFREQ) {
        int tok = t / NFREQ, f = t % NFREQ;
        const float* xv = xs[tok];
        float re = 0.f, im = 0.f;
        int m = 0;
        #pragma unroll 8
        for (int n = 0; n < PSZ; n++) {
            re += xv[n] * twc[m];
            im += xv[n] * tws[m];
            m += f;
            if (m >= PSZ) m -= PSZ;
        }
        g_spec[((size_t)blockIdx.x * 2 + tok) * NFREQ + f] = sqrtf(re * re + im * im) * 0.005f;
    }
}

// ---------------------------------------------------------------------------
__global__ __launch_bounds__(256) void k_mkpe(const float* __restrict__ gns,
                                              const float* __restrict__ gnb,
                                              const float* __restrict__ spec_b) {
    int i = blockIdx.x * 256 + threadIdx.x;
    if (i >= PETOT) return;
    int tkn = i / DMD, d = i % DMD;
    int b = tkn / RR, r = tkn % RR;
    int ic = d >> 3;
    int bg = b * 5 + ic / 5;
    float raw = g_bufA[(((size_t)b * C25 + ic) * RR + r) * W8 + (d & 7)];
    float v = (raw - g_mean[bg]) * g_rstd[bg] * gns[ic] + gnb[ic];
    g_pe[i] = gelu_exact(v) + spec_b[d];
}

// ---------------------------------------------------------------------------
// generic fp32 SGEMM (spectral projection only): C += A @ B
// ---------------------------------------------------------------------------
__global__ __launch_bounds__(256) void k_sgemm(const float* __restrict__ A,
                                               const float* __restrict__ Bm,
                                               float* __restrict__ C,
                                               int M, int N, int K,
                                               int lda, int bk, int bn, int ldc,
                                               int accFlag) {
    __shared__ __align__(16) float As[8][68];
    __shared__ __align__(16) float Bs[8][68];
    int m0 = blockIdx.y * 64, n0 = blockIdx.x * 64;
    int t = threadIdx.x;
    int tx = t % 16, ty = t / 16;
    float acc[4][4];
    #pragma unroll
    for (int i = 0; i < 4; i++)
        #pragma unroll
        for (int j = 0; j < 4; j++) acc[i][j] = 0.f;

    int nk = (K + 7) / 8;
    for (int kb = 0; kb < nk; kb++) {
        int k0 = kb * 8;
        {
            int kk = t & 7, mm = t >> 3;
            int k = k0 + kk;
            #pragma unroll
            for (int hh = 0; hh < 2; hh++) {
                int m = m0 + mm + hh * 32;
                As[kk][mm + hh * 32] = (k < K && m < M) ? A[(size_t)m * lda + k] : 0.f;
            }
        }
        {
            int kk = t & 7, nn = t >> 3;
            int k = k0 + kk;
            #pragma unroll
            for (int hh = 0; hh < 2; hh++) {
                int n = n0 + nn + hh * 32;
                Bs[kk][nn + hh * 32] = (k < K && n < N) ? Bm[(size_t)k * bk + (size_t)n * bn] : 0.f;
            }
        }
        __syncthreads();
        #pragma unroll
        for (int kk = 0; kk < 8; kk++) {
            float4 av = *reinterpret_cast<const float4*>(&As[kk][ty * 4]);
            float4 bv = *reinterpret_cast<const float4*>(&Bs[kk][tx * 4]);
            float a[4] = {av.x, av.y, av.z, av.w};
            float bb[4] = {bv.x, bv.y, bv.z, bv.w};
            #pragma unroll
            for (int i = 0; i < 4; i++)
                #pragma unroll
                for (int j = 0; j < 4; j++) acc[i][j] += a[i] * bb[j];
        }
        __syncthreads();
    }
    #pragma unroll
    for (int i = 0; i < 4; i++) {
        int m = m0 + ty * 4 + i;
        if (m >= M) continue;
        #pragma unroll
        for (int j = 0; j < 4; j++) {
            int n = n0 + tx * 4 + j;
            if (n < N) {
                size_t o = (size_t)m * ldc + n;
                C[o] = accFlag ? (C[o] + acc[i][j]) : acc[i][j];
            }
        }
    }
}

// ---------------------------------------------------------------------------
__global__ __launch_bounds__(256) void k_c0(const float* __restrict__ cb,
                                            const float* __restrict__ inp_b) {
    int k = blockIdx.x;
    float s = 0.f, sb = 0.f;
    for (int l = threadIdx.x; l < LLM; l += 256) {
        float v = cb[(size_t)k * LLM + l];
        s += v * v;
        sb += inp_b[l] * v;
    }
    __shared__ float r1[256], r2[256];
    int t = threadIdx.x;
    r1[t] = s; r2[t] = sb;
    __syncthreads();
    for (int st = 128; st > 0; st >>= 1) {
        if (t < st) { r1[t] += r1[t + st]; r2[t] += r2[t + st]; }
        __syncthreads();
    }
    if (t == 0) g_c0[k] = 0.5f * r1[0] - r2[0];
}

// ---------------------------------------------------------------------------
// k_prep2: dual GEMM sharing A-tile (cb); MOV-free FMA2 inner loop.
//   G[m,n]    = sum_k cb[m,k] * inp_w[k,n]
//   cout[m,n] = sum_k cb[m,k] * outp_w[n,k]
// M=4096, N=200(->64 tiles x4), K=4096. Tile 64x64, micro 4x4.
// ---------------------------------------------------------------------------
__global__ __launch_bounds__(256) void k_prep2(const float* __restrict__ cb,
                                               const float* __restrict__ inp_w,
                                               const float* __restrict__ outp_w) {
    __shared__ __align__(16) unsigned long long As2[2][8][64];  // dup'd A
    __shared__ __align__(16) float B1s[2][8][64];
    __shared__ __align__(16) float B2s[2][8][64];
    const int t = threadIdx.x;
    const int tx = t & 15, ty = t >> 4;
    const int lk = t & 7, lm = t >> 3;       // 8 x 32
    const int nn = t & 63, kq = t >> 6;      // 64 x 4
    const int m0 = blockIdx.y * 64, n0 = blockIdx.x * 64;

    unsigned long long a1[4][2], a2[4][2];
    #pragma unroll
    for (int i = 0; i < 4; i++)
        #pragma unroll
        for (int jp = 0; jp < 2; jp++) { a1[i][jp] = 0ULL; a2[i][jp] = 0ULL; }

    // prologue: tile 0
    #pragma unroll
    for (int h = 0; h < 2; h++) {
        float a = cb[(size_t)(m0 + lm + h * 32) * LLM + lk];
        unsigned long long ad; PACKDUP(ad, a);
        As2[0][lk][lm + h * 32] = ad;
        int kk = kq + h * 4;
        B1s[0][kk][nn] = (n0 + nn < DMD) ? inp_w[(size_t)kk * DMD + n0 + nn] : 0.f;
        B2s[0][lk][lm + h * 32] = (n0 + lm + h * 32 < DMD)
            ? outp_w[(size_t)(n0 + lm + h * 32) * LLM + lk] : 0.f;
    }
    __syncthreads();
    for (int kb = 0; kb < LLM / 8; kb++) {
        int cur = kb & 1, nxt = cur ^ 1;
        if (kb < LLM / 8 - 1) {
            int k0 = (kb + 1) * 8;
            #pragma unroll
            for (int h = 0; h < 2; h++) {
                float a = cb[(size_t)(m0 + lm + h * 32) * LLM + k0 + lk];
                unsigned long long ad; PACKDUP(ad, a);
                As2[nxt][lk][lm + h * 32] = ad;
                int kk = kq + h * 4;
                B1s[nxt][kk][nn] = (n0 + nn < DMD) ? inp_w[(size_t)(k0 + kk) * DMD + n0 + nn] : 0.f;
                B2s[nxt][lk][lm + h * 32] = (n0 + lm + h * 32 < DMD)
                    ? outp_w[(size_t)(n0 + lm + h * 32) * LLM + k0 + lk] : 0.f;
            }
        }
        #pragma unroll
        for (int kk = 0; kk < 8; kk++) {
            ulonglong2 aA = *reinterpret_cast<const ulonglong2*>(&As2[cur][kk][ty * 4]);
            ulonglong2 aB = *reinterpret_cast<const ulonglong2*>(&As2[cur][kk][ty * 4 + 2]);
            ulonglong2 b1 = *reinterpret_cast<const ulonglong2*>(&B1s[cur][kk][tx * 4]);
            ulonglong2 b2 = *reinterpret_cast<const ulonglong2*>(&B2s[cur][kk][tx * 4]);
            unsigned long long ap[4] = {aA.x, aA.y, aB.x, aB.y};
            #pragma unroll
            for (int i = 0; i < 4; i++) {
                FMA2(a1[i][0], ap[i], b1.x);
                FMA2(a1[i][1], ap[i], b1.y);
                FMA2(a2[i][0], ap[i], b2.x);
                FMA2(a2[i][1], ap[i], b2.y);
            }
        }
        __syncthreads();
    }
    // epilogue
    #pragma unroll
    for (int i = 0; i < 4; i++) {
        int m = m0 + ty * 4 + i;
        #pragma unroll
        for (int jp = 0; jp < 2; jp++) {
            unsigned lo, hi;
            int n = n0 + tx * 4 + jp * 2;
            UNPK2(lo, hi, a1[i][jp]);
            if (n < DMD)     g_G[(size_t)m * DMD + n]     = __uint_as_float(lo);
            if (n + 1 < DMD) g_G[(size_t)m * DMD + n + 1] = __uint_as_float(hi);
            UNPK2(lo, hi, a2[i][jp]);
            if (n < DMD)     g_cout[(size_t)m * DMD + n]     = __uint_as_float(lo);
            if (n + 1 < DMD) g_cout[(size_t)m * DMD + n + 1] = __uint_as_float(hi);
        }
    }
}

// ---------------------------------------------------------------------------
__global__ __launch_bounds__(256) void k_pos(const float* __restrict__ pw,
                                             const float* __restrict__ pb) {
    int b = blockIdx.x / DMD, d = blockIdx.x % DMD;
    __shared__ float mp[RR];
    __shared__ float w[133];
    int t = threadIdx.x;
    for (int i = t; i < RR; i += 256)
        mp[i] = g_pe[((size_t)b * RR + i) * DMD + d];
    if (t < 133) w[t] = pw[d * 133 + t];
    __syncthreads();
    float bias = pb[d];
    for (int o = t; o < RR; o += 256) {
        int ch = o / NPP, pn = o % NPP;
        float acc = mp[o] + bias;
        #pragma unroll
        for (int i = 0; i < 19; i++) {
            int ci = ch + i - 9;
            if (ci < 0 || ci >= CHN) continue;
            int base = ci * NPP;
            #pragma unroll
            for (int j = 0; j < 7; j++) {
                int pj = pn + j - 3;
                if (pj < 0 || pj >= NPP) continue;
                acc += mp[base + pj] * w[i * 7 + j];
            }
        }
        g_bufA[((size_t)b * RR + o) * DMD + d] = acc;
    }
}

// ---------------------------------------------------------------------------
// k_score3: s[t,k] = c0[k] - pe2[t].G[k]; idx[t] = first argmin.
// Tile 128M x 128N, micro 8x8, grid 143 (last block partial; loads clamped).
// MOV-free FMA2 inner loop (dup-A smem, u64 B loads).
// ---------------------------------------------------------------------------
__global__ __launch_bounds__(256) void k_score3() {
    __shared__ __align__(16) unsigned long long As2[2][8][128];  // 16 KB
    __shared__ __align__(16) float Bs[2][8][128];                // 8 KB
    __shared__ float rv[128][17];                                // 8.7 KB
    __shared__ int   rix[128][17];                               // 8.7 KB
    const int t = threadIdx.x;
    const int tx = t & 15, ty = t >> 4;
    const int lk = t & 7, lm = t >> 3;     // 8 k x 32 rows
    const int m0 = blockIdx.x * 128;
    float bestv[8]; int besti[8];
    #pragma unroll
    for (int i = 0; i < 8; i++) { bestv[i] = INFINITY; besti[i] = 0; }

    for (int nb = 0; nb < 32; nb++) {
        const int n0 = nb * 128;
        __syncthreads();   // smem reuse vs previous iteration
        // prologue kb = 0
        #pragma unroll
        for (int h = 0; h < 4; h++) {
            int m = m0 + lm + h * 32; if (m > TT - 1) m = TT - 1;
            float a = g_bufA[(size_t)m * DMD + lk];
            unsigned long long ad; PACKDUP(ad, a);
            As2[0][lk][lm + h * 32] = ad;
            Bs[0][lk][lm + h * 32] = g_G[(size_t)(n0 + lm + h * 32) * DMD + lk];
        }
        unsigned long long acc[8][4];
        #pragma unroll
        for (int i = 0; i < 8; i++)
            #pragma unroll
            for (int jp = 0; jp < 4; jp++) acc[i][jp] = 0ULL;
        __syncthreads();
        for (int kb = 0; kb < 25; kb++) {
            int cur = kb & 1, nxt = cur ^ 1;
            if (kb < 24) {
                int k = (kb + 1) * 8 + lk;
                #pragma unroll
                for (int h = 0; h < 4; h++) {
                    int m = m0 + lm + h * 32; if (m > TT - 1) m = TT - 1;
                    float a = g_bufA[(size_t)m * DMD + k];
                    unsigned long long ad; PACKDUP(ad, a);
                    As2[nxt][lk][lm + h * 32] = ad;
                    Bs[nxt][lk][lm + h * 32] = g_G[(size_t)(n0 + lm + h * 32) * DMD + k];
                }
            }
            #pragma unroll
            for (int kk = 0; kk < 8; kk++) {
                ulonglong2 a01 = *reinterpret_cast<const ulonglong2*>(&As2[cur][kk][ty * 8]);
                ulonglong2 a23 = *reinterpret_cast<const ulonglong2*>(&As2[cur][kk][ty * 8 + 2]);
                ulonglong2 a45 = *reinterpret_cast<const ulonglong2*>(&As2[cur][kk][ty * 8 + 4]);
                ulonglong2 a67 = *reinterpret_cast<const ulonglong2*>(&As2[cur][kk][ty * 8 + 6]);
                ulonglong2 bq0 = *reinterpret_cast<const ulonglong2*>(&Bs[cur][kk][tx * 8]);
                ulonglong2 bq1 = *reinterpret_cast<const ulonglong2*>(&Bs[cur][kk][tx * 8 + 4]);
                unsigned long long ap[8] = {a01.x, a01.y, a23.x, a23.y,
                                            a45.x, a45.y, a67.x, a67.y};
                unsigned long long bp[4] = {bq0.x, bq0.y, bq1.x, bq1.y};
                #pragma unroll
                for (int i = 0; i < 8; i++) {
                    FMA2(acc[i][0], ap[i], bp[0]);
                    FMA2(acc[i][1], ap[i], bp[1]);
                    FMA2(acc[i][2], ap[i], bp[2]);
                    FMA2(acc[i][3], ap[i], bp[3]);
                }
            }
            __syncthreads();
        }
        // running argmin epilogue (ascending n within thread = first-min)
        float4 cA = *reinterpret_cast<const float4*>(&g_c0[n0 + tx * 8]);
        float4 cB = *reinterpret_cast<const float4*>(&g_c0[n0 + tx * 8 + 4]);
        float cv[8] = {cA.x, cA.y, cA.z, cA.w, cB.x, cB.y, cB.z, cB.w};
        #pragma unroll
        for (int jp = 0; jp < 4; jp++) {
            #pragma unroll
            for (int i = 0; i < 8; i++) {
                unsigned lo, hi;
                UNPK2(lo, hi, acc[i][jp]);
                float s0 = cv[2 * jp]     - __uint_as_float(lo);
                float s1 = cv[2 * jp + 1] - __uint_as_float(hi);
                int nbase = n0 + tx * 8 + 2 * jp;
                if (s0 < bestv[i]) { bestv[i] = s0; besti[i] = nbase; }
                if (s1 < bestv[i]) { bestv[i] = s1; besti[i] = nbase + 1; }
            }
        }
    }
    #pragma unroll
    for (int i = 0; i < 8; i++) { rv[ty * 8 + i][tx] = bestv[i]; rix[ty * 8 + i][tx] = besti[i]; }
    __syncthreads();
    if (t < 128) {
        float bv = rv[t][0]; int bi_ = rix[t][0];
        #pragma unroll
        for (int xx = 1; xx < 16; xx++) {
            float v = rv[t][xx]; int ii = rix[t][xx];
            if (v < bv || (v == bv && ii < bi_)) { bv = v; bi_ = ii; }
        }
        if (m0 + t < TT) g_idx[m0 + t] = bi_;
    }
}

// ---------------------------------------------------------------------------
__global__ __launch_bounds__(256) void k_gather(const float* __restrict__ outp_b,
                                                float* __restrict__ out) {
    int i = blockIdx.x * 256 + threadIdx.x;
    if (i >= PETOT) return;
    int tkn = i / DMD, d = i % DMD;
    out[i] = g_cout[(size_t)g_idx[tkn] * DMD + d] + outp_b[d];
}

// ---------------------------------------------------------------------------
extern "C" void kernel_launch(void* const* d_in, const int* in_sizes, int n_in,
                              void* d_out, int out_size) {
    const float* x      = (const float*)d_in[0];
    const float* c1w    = (const float*)d_in[1];
    const float* c1b    = (const float*)d_in[2];
    const float* gn1s   = (const float*)d_in[3];
    const float* gn1b   = (const float*)d_in[4];
    const float* c2w    = (const float*)d_in[5];
    const float* c2b    = (const float*)d_in[6];
    const float* gn2s   = (const float*)d_in[7];
    const float* gn2b   = (const float*)d_in[8];
    const float* c3w    = (const float*)d_in[9];
    const float* c3b    = (const float*)d_in[10];
    const float* gn3s   = (const float*)d_in[11];
    const float* gn3b   = (const float*)d_in[12];
    const float* spec_w = (const float*)d_in[13];
    const float* spec_b = (const float*)d_in[14];
    const float* pos_w  = (const float*)d_in[15];
    const float* pos_b  = (const float*)d_in[16];
    const float* inp_w  = (const float*)d_in[17];
    const float* inp_b  = (const float*)d_in[18];
    const float* cb     = (const float*)d_in[19];
    const float* outp_w = (const float*)d_in[20];
    const float* outp_b = (const float*)d_in[21];
    float* out = (float*)d_out;

    float *pSpec, *pBufA, *pBufB, *pPe;
    cudaGetSymbolAddress((void**)&pSpec, g_spec);
    cudaGetSymbolAddress((void**)&pBufA, g_bufA);
    cudaGetSymbolAddress((void**)&pBufB, g_bufB);
    cudaGetSymbolAddress((void**)&pPe,   g_pe);

    const int EW = (HTOT + 255) / 256;

    // --- VQ precomputations ---
    k_prep2<<<dim3(4, 64), 256>>>(cb, inp_w, outp_w);
    k_c0<<<KCB, 256>>>(cb, inp_b);

    // --- conv / GN / GELU chain ---
    k_conv1<<<TT, 256>>>(x, c1w, c1b);
    k_gnstats<<<BB * 5, 256>>>(pBufA);
    k_conv3x<<<BB * 72, 256>>>(pBufA, c2w, c2b, gn1s, gn1b, pBufB);
    k_gnstats<<<BB * 5, 256>>>(pBufB);
    k_conv3x<<<BB * 72, 256>>>(pBufB, c3w, c3b, gn2s, gn2b, pBufA);
    k_gnstats<<<BB * 5, 256>>>(pBufA);

    // --- spectral branch ---
    k_dft<<<TT / 2, 256>>>(x);
    k_mkpe<<<EW, 256>>>(gn3s, gn3b, spec_b);
    k_sgemm<<<dim3((DMD + 63) / 64, TT / 64), 256>>>(pSpec, spec_w, pPe,
        TT, DMD, NFREQ, NFREQ, 1, NFREQ, DMD, 1);

    // --- depthwise positional conv ---
    k_pos<<<BB * DMD, 256>>>(pos_w, pos_b);

    // --- fused score GEMM + argmin ---
    k_score3<<<(TT + 127) / 128, 256>>>();

    // --- output gather ---
    k_gather<<<EW, 256>>>(outp_b, out);
}